// round 8
// baseline (speedup 1.0000x reference)
#include <cuda_runtime.h>
#include <math.h>
#include <cstdint>

#define Bq   8
#define Nq   2048
#define Dq   1024
#define Eq   8
#define Hq   4096
#define CAP  320
#define NTOK (Bq*Nq)
#define OUT_MAIN ((size_t)NTOK*Dq)

__device__ int   d_meta[NTOK];
__device__ float d_g1[NTOK];
__device__ float d_g2[NTOK];
__device__ int   d_a1[NTOK];
__device__ int   d_a2[NTOK];
__device__ float d_proxy[Bq*Eq];
__device__ int   d_slotTok[Eq*Bq*CAP];
__device__ float d_h  [(size_t)Eq*Bq*CAP*Hq];   // tf32-valued post-GELU hidden
__device__ float d_eo [(size_t)Eq*Bq*CAP*Dq];
__device__ float d_xt [(size_t)NTOK*Dq];        // tf32-rounded x
__device__ float d_w1t[(size_t)Eq*Dq*Hq];       // [e][n][k] tf32
__device__ float d_w2t[(size_t)Eq*Hq*Dq];       // [e][n][k] tf32
__device__ float d_zero[4352];                  // static zero-init

// ---------------- helpers ----------------
__device__ __forceinline__ uint32_t smem_u32(const void* p) {
    uint32_t a;
    asm("{ .reg .u64 t; cvta.to.shared.u64 t, %1; cvt.u32.u64 %0, t; }" : "=r"(a) : "l"(p));
    return a;
}
__device__ __forceinline__ uint32_t f2tf32(float x) {
    uint32_t r;
    asm("cvt.rna.tf32.f32 %0, %1;" : "=r"(r) : "f"(x));
    return r;
}
__device__ __forceinline__ void mma_tf32(float* d, const uint32_t* a, const uint32_t* b) {
    asm volatile(
        "mma.sync.aligned.m16n8k8.row.col.f32.tf32.tf32.f32 "
        "{%0,%1,%2,%3}, {%4,%5,%6,%7}, {%8,%9}, {%0,%1,%2,%3};\n"
        : "+f"(d[0]), "+f"(d[1]), "+f"(d[2]), "+f"(d[3])
        : "r"(a[0]), "r"(a[1]), "r"(a[2]), "r"(a[3]), "r"(b[0]), "r"(b[1]));
}
__device__ __forceinline__ void ldsm4(uint32_t* r, uint32_t addr) {
    asm volatile("ldmatrix.sync.aligned.m8n8.x4.shared.b16 {%0,%1,%2,%3}, [%4];"
        : "=r"(r[0]), "=r"(r[1]), "=r"(r[2]), "=r"(r[3]) : "r"(addr));
}
__device__ __forceinline__ void cpa16(uint32_t dst, const float* src) {
    asm volatile("cp.async.cg.shared.global [%0], [%1], 16;" :: "r"(dst), "l"(src) : "memory");
}
#define CP_COMMIT() asm volatile("cp.async.commit_group;" ::: "memory")
#define CP_WAIT4()  asm volatile("cp.async.wait_group 4;" ::: "memory")

// ---------------- init ----------------
__global__ void init_kernel() {
    int t = threadIdx.x;
    if (t < Bq*Eq) d_proxy[t] = 0.f;
}

// ---------------- pre-convert x -> tf32 ----------------
__global__ __launch_bounds__(256) void conv_x(const float* __restrict__ x) {
    size_t i = ((size_t)blockIdx.x * 256 + threadIdx.x) * 4;
    float4 v = *(const float4*)(x + i);
    v.x = __uint_as_float(f2tf32(v.x));
    v.y = __uint_as_float(f2tf32(v.y));
    v.z = __uint_as_float(f2tf32(v.z));
    v.w = __uint_as_float(f2tf32(v.w));
    *(float4*)(d_xt + i) = v;
}

// ---------------- pre-convert + transpose weights: Wt[e][n][k] = rna(W[e][k][n]) ----------------
template<int Kd, int Nc>
__global__ __launch_bounds__(256) void conv_w(const float* __restrict__ W, float* __restrict__ Wt) {
    __shared__ float t[32][33];
    const int e  = blockIdx.z;
    const int k0 = blockIdx.y * 32, n0 = blockIdx.x * 32;
    const float* src = W  + (size_t)e * Kd * Nc;
    float*       dst = Wt + (size_t)e * Kd * Nc;
    const int lx = threadIdx.x & 31, ly = threadIdx.x >> 5;
    #pragma unroll
    for (int yy = ly; yy < 32; yy += 8)
        t[yy][lx] = src[(size_t)(k0 + yy) * Nc + n0 + lx];
    __syncthreads();
    #pragma unroll
    for (int yy = ly; yy < 32; yy += 8)
        dst[(size_t)(n0 + yy) * Kd + k0 + lx] = __uint_as_float(f2tf32(t[lx][yy]));
}

// ---------------- gating ----------------
__global__ __launch_bounds__(256) void gating_kernel(
    const float* __restrict__ x, const float* __restrict__ wg,
    const float* __restrict__ rnd)
{
    __shared__ float s_wg[Eq][Dq];
    __shared__ float s_proxy[Eq];
    int tid = threadIdx.x;
    for (int f = tid; f < Dq*Eq; f += 256) {
        int d = f >> 3, e = f & 7;
        s_wg[e][d] = wg[f];
    }
    if (tid < Eq) s_proxy[tid] = 0.f;
    __syncthreads();

    int warp = tid >> 5, lane = tid & 31;
    int tok  = blockIdx.x * 8 + warp;
    const float* xp = x + (size_t)tok * Dq;

    float acc[Eq];
    #pragma unroll
    for (int e = 0; e < Eq; ++e) acc[e] = 0.f;
    #pragma unroll 4
    for (int i = 0; i < Dq/32; ++i) {
        float xv = xp[i*32 + lane];
        #pragma unroll
        for (int e = 0; e < Eq; ++e) acc[e] += xv * s_wg[e][i*32 + lane];
    }
    #pragma unroll
    for (int off = 16; off; off >>= 1)
        #pragma unroll
        for (int e = 0; e < Eq; ++e)
            acc[e] += __shfl_down_sync(0xffffffffu, acc[e], off);

    if (lane == 0) {
        float mx = acc[0];
        #pragma unroll
        for (int e = 1; e < Eq; ++e) mx = fmaxf(mx, acc[e]);
        float raw[Eq]; float s = 0.f;
        #pragma unroll
        for (int e = 0; e < Eq; ++e) { raw[e] = expf(acc[e] - mx); s += raw[e]; }
        float inv = 1.f / s;
        #pragma unroll
        for (int e = 0; e < Eq; ++e) raw[e] *= inv;
        int i1 = 0; float g1 = raw[0];
        #pragma unroll
        for (int e = 1; e < Eq; ++e) if (raw[e] > g1) { g1 = raw[e]; i1 = e; }
        int i2 = -1; float g2 = -1.f;
        #pragma unroll
        for (int e = 0; e < Eq; ++e) if (e != i1 && raw[e] > g2) { g2 = raw[e]; i2 = e; }
        float denom = g1 + g2 + 1e-9f;
        float g1n = g1 / denom, g2n = g2 / denom;
        int keep2 = (rnd[tok] < (g2n / 0.2f)) ? 1 : 0;
        d_meta[tok] = i1 | (i2 << 4) | (keep2 << 8);
        d_g1[tok] = g1n;
        d_g2[tok] = g2n;
        #pragma unroll
        for (int e = 0; e < Eq; ++e) atomicAdd(&s_proxy[e], raw[e]);
    }
    __syncthreads();
    if (tid < Eq) {
        int b = (blockIdx.x * 8) >> 11;
        atomicAdd(&d_proxy[b*Eq + tid], s_proxy[tid]);
    }
}

// ---------------- scan ----------------
__global__ void scan_kernel(float* __restrict__ dout, int out_size)
{
    __shared__ int   s_meta[2048];
    __shared__ float s_red[64];
    int t = threadIdx.x;
    int b = t >> 3, e = t & 7;
    int g = e * Bq + b;
    for (int j = 0; j < CAP; ++j) d_slotTok[g*CAP + j] = -1;
    int c1 = 0;
    for (int ch = 0; ch < 8; ++ch) {
        __syncthreads();
        for (int i = t; i < 2048; i += 64) {
            int bb = i >> 8, ii = i & 255;
            s_meta[i] = d_meta[bb*Nq + ch*256 + ii];
        }
        __syncthreads();
        for (int ii = 0; ii < 256; ++ii) {
            int meta = s_meta[b*256 + ii];
            if ((meta & 15) == e) {
                int n = ch*256 + ii;
                if (c1 < CAP) {
                    d_slotTok[g*CAP + c1] = n;
                    d_a1[b*Nq + n] = (e << 10) | c1;
                } else d_a1[b*Nq + n] = -1;
                c1++;
            }
        }
    }
    int c1raw = c1;
    int pos = (c1 < CAP) ? c1 : CAP;
    for (int ch = 0; ch < 8; ++ch) {
        __syncthreads();
        for (int i = t; i < 2048; i += 64) {
            int bb = i >> 8, ii = i & 255;
            s_meta[i] = d_meta[bb*Nq + ch*256 + ii];
        }
        __syncthreads();
        for (int ii = 0; ii < 256; ++ii) {
            int meta = s_meta[b*256 + ii];
            if (((meta >> 4) & 15) == e) {
                int n = ch*256 + ii;
                if ((meta >> 8) & 1) {
                    if (pos < CAP) {
                        d_slotTok[g*CAP + pos] = n;
                        d_a2[b*Nq + n] = (e << 10) | pos;
                    } else d_a2[b*Nq + n] = -1;
                    pos++;
                } else d_a2[b*Nq + n] = -1;
            }
        }
    }
    s_red[t] = (d_proxy[b*Eq + e] / (float)Nq) * ((float)c1raw / (float)Nq);
    __syncthreads();
    if (t == 0) {
        float s = 0.f;
        for (int i = 0; i < 64; ++i) s += s_red[i];
        if ((size_t)out_size > OUT_MAIN) dout[OUT_MAIN] = s * 0.01f;
    }
}

// ---------------- tf32 mma.sync grouped GEMM: cp.async 5-stage pipeline ----------------
// CTA 128x128, 8 warps (2m x 4n), warp 64x32. K in 32-chunks.
// Stage s (s=0..4) at s*32768: A[128r][32k] @ +0, B[128n][32k] @ +16384.
// Swizzle: off = row*128 + 16*(slot ^ (row&7)), slot = k/4.
// sPtr @163840 (1KB), sBias @164864 (512B). Total 165376 (1 CTA/SM, no reg cap).
// Group discipline: EXACTLY one commit per iteration (empty at tail);
// wait_group 4 then guarantees group ch is complete before reading buffer ch%5.
#define SMEM_FFN 165376

template<int PHASE>
__global__ __launch_bounds__(256) void ffn_mma(const float* __restrict__ A_src,
                                               const float* __restrict__ Wt,
                                               const float* __restrict__ Bias)
{
    constexpr int Kdim  = (PHASE == 1) ? Dq : Hq;
    constexpr int Ncols = (PHASE == 1) ? Hq : Dq;
    constexpr int NCH   = Kdim / 32;

    extern __shared__ char smem[];
    const float** sPtr  = (const float**)(smem + 163840);
    float*        sBias = (float*)(smem + 164864);

    const int tid  = threadIdx.x;
    const int wid  = tid >> 5, lane = tid & 31;
    const int g8   = lane >> 2, tg = lane & 3;
    const int n0   = blockIdx.x * 128;
    const int m0   = blockIdx.y * 128;
    const int grp  = blockIdx.z;
    const int e    = grp >> 3, b = grp & 7;
    const int wm   = wid & 1, wn = wid >> 1;
    const bool active = (m0 + wm*64) < CAP;

    if (tid < 128) {
        int c = m0 + tid;
        const float* p = d_zero;
        if (c < CAP) {
            if (PHASE == 1) {
                int tok = d_slotTok[grp*CAP + c];
                if (tok >= 0) p = d_xt + ((size_t)(b*Nq) + tok) * Dq;
            } else {
                p = d_h + ((size_t)grp*CAP + c) * Hq;
            }
        }
        sPtr[tid]  = p;
        sBias[tid] = Bias[(size_t)e * Ncols + n0 + tid];
    }
    __syncthreads();

    const uint32_t sb = smem_u32(smem);

    // per-thread cp.async geometry (A and B symmetric: 128 rows x 32 k)
    const int row = tid >> 1, fb = (tid & 1) * 4;
    uint32_t dRel[4];
    #pragma unroll
    for (int i = 0; i < 4; ++i)
        dRel[i] = (uint32_t)(row*128 + 16*((fb + i) ^ (row & 7)));
    const float* aRow = sPtr[row];
    const float* bRow = Wt + (size_t)e * Kdim * Ncols + (size_t)(n0 + row) * Kdim;

    #define ISSUE(ch) do { \
        const uint32_t so = sb + (uint32_t)(((ch) % 5) * 32768); \
        const float* asrc = aRow + (ch)*32 + fb*4; \
        const float* bsrc = bRow + (ch)*32 + fb*4; \
        _Pragma("unroll") \
        for (int i = 0; i < 4; ++i) cpa16(so + dRel[i], asrc + i*4); \
        _Pragma("unroll") \
        for (int i = 0; i < 4; ++i) cpa16(so + 16384u + dRel[i], bsrc + i*4); \
        CP_COMMIT(); \
    } while (0)

    // ldmatrix geometry
    const int hiA = lane >> 4;
    const uint32_t aBaseRel = (uint32_t)(wm*64 + ((lane>>3)&1)*8 + (lane&7)) * 128u;
    const uint32_t bBaseRel = 16384u + (uint32_t)(wn*32 + (lane>>4)*8 + (lane&7)) * 128u;
    uint32_t aSw[4], bSw[4];
    #pragma unroll
    for (int ks = 0; ks < 4; ++ks) {
        aSw[ks] = 16u * (uint32_t)((2*ks + hiA) ^ (lane & 7));
        bSw[ks] = 16u * (uint32_t)((2*ks + ((lane>>3)&1)) ^ (lane & 7));
    }

    float acc[4][4][4];
    #pragma unroll
    for (int mi = 0; mi < 4; ++mi)
        #pragma unroll
        for (int ni = 0; ni < 4; ++ni)
            #pragma unroll
            for (int q = 0; q < 4; ++q) acc[mi][ni][q] = 0.f;

    ISSUE(0);
    ISSUE(1);
    ISSUE(2);
    ISSUE(3);

    for (int ch = 0; ch < NCH; ++ch) {
        // uniform group counting: one commit per iteration.
        if (ch + 4 < NCH) ISSUE(ch + 4); else CP_COMMIT();
        CP_WAIT4();
        __syncthreads();

        if (active) {
            const uint32_t bufOff = sb + (uint32_t)((ch % 5) * 32768);
            #pragma unroll
            for (int ks = 0; ks < 4; ++ks) {
                uint32_t af[4][4], bf[2][4];
                const uint32_t ao = bufOff + aBaseRel + aSw[ks];
                const uint32_t bo = bufOff + bBaseRel + bSw[ks];
                #pragma unroll
                for (int mi = 0; mi < 4; ++mi)
                    ldsm4(af[mi], ao + (uint32_t)(mi*2048));
                ldsm4(bf[0], bo);
                ldsm4(bf[1], bo + 2048u);
                #pragma unroll
                for (int mi = 0; mi < 4; ++mi) {
                    mma_tf32(acc[mi][0], af[mi], &bf[0][0]);
                    mma_tf32(acc[mi][1], af[mi], &bf[0][2]);
                    mma_tf32(acc[mi][2], af[mi], &bf[1][0]);
                    mma_tf32(acc[mi][3], af[mi], &bf[1][2]);
                }
            }
        }
        __syncthreads();
    }
    #undef ISSUE

    // epilogue
    float* Outp = (PHASE == 1) ? d_h : d_eo;
    #pragma unroll
    for (int mi = 0; mi < 4; ++mi) {
        #pragma unroll
        for (int h = 0; h < 2; ++h) {
            int c = m0 + wm*64 + mi*16 + g8 + h*8;
            if (c < CAP) {
                float* orow = Outp + ((size_t)grp*CAP + c) * Ncols + n0;
                #pragma unroll
                for (int ni = 0; ni < 4; ++ni) {
                    int col = wn*32 + ni*8 + 2*tg;
                    float v0 = acc[mi][ni][2*h]     + sBias[col];
                    float v1 = acc[mi][ni][2*h + 1] + sBias[col + 1];
                    if (PHASE == 1) {
                        v0 = 0.5f * v0 * (1.0f + erff(v0 * 0.70710678118654752f));
                        v1 = 0.5f * v1 * (1.0f + erff(v1 * 0.70710678118654752f));
                        v0 = __uint_as_float(f2tf32(v0));   // d_h feeds GEMM2 as tf32
                        v1 = __uint_as_float(f2tf32(v1));
                    }
                    float2 v = make_float2(v0, v1);
                    *(float2*)(orow + col) = v;
                }
            }
        }
    }
}

// ---------------- combine ----------------
__global__ __launch_bounds__(256) void combine_kernel(float* __restrict__ out)
{
    int tok = blockIdx.x;
    int b   = tok >> 11;
    int a1  = d_a1[tok], a2 = d_a2[tok];
    float g1 = d_g1[tok], g2 = d_g2[tok];
    int off = threadIdx.x * 4;

    float4 v = make_float4(0.f, 0.f, 0.f, 0.f);
    if (a1 >= 0) {
        size_t row = ((size_t)((a1 >> 10) * Bq + b)) * CAP + (a1 & 1023);
        const float4 s = *(const float4*)(d_eo + row * Dq + off);
        v.x = g1 * s.x; v.y = g1 * s.y; v.z = g1 * s.z; v.w = g1 * s.w;
    }
    if (a2 >= 0) {
        size_t row = ((size_t)((a2 >> 10) * Bq + b)) * CAP + (a2 & 1023);
        const float4 s = *(const float4*)(d_eo + row * Dq + off);
        v.x += g2 * s.x; v.y += g2 * s.y; v.z += g2 * s.z; v.w += g2 * s.w;
    }
    *(float4*)(out + (size_t)tok * Dq + off) = v;
}

// ---------------- launch ----------------
extern "C" void kernel_launch(void* const* d_in, const int* in_sizes, int n_in,
                              void* d_out, int out_size)
{
    const float* x  = (const float*)d_in[0];
    const float* wg = (const float*)d_in[1];
    const float* w1 = (const float*)d_in[2];
    const float* b1 = (const float*)d_in[3];
    const float* w2 = (const float*)d_in[4];
    const float* b2 = (const float*)d_in[5];
    const float* rp = (const float*)d_in[6];
    float* out = (float*)d_out;

    cudaFuncSetAttribute(ffn_mma<1>, cudaFuncAttributeMaxDynamicSharedMemorySize, SMEM_FFN);
    cudaFuncSetAttribute(ffn_mma<2>, cudaFuncAttributeMaxDynamicSharedMemorySize, SMEM_FFN);

    init_kernel<<<1, 64>>>();
    conv_x<<<NTOK*Dq/1024, 256>>>(x);
    conv_w<Dq, Hq><<<dim3(Hq/32, Dq/32, Eq), 256>>>(w1, d_w1t);
    conv_w<Hq, Dq><<<dim3(Dq/32, Hq/32, Eq), 256>>>(w2, d_w2t);
    gating_kernel<<<NTOK/8, 256>>>(x, wg, rp);
    scan_kernel<<<1, 64>>>(out, out_size);

    ffn_mma<1><<<dim3(Hq/128, 3, Eq*Bq), 256, SMEM_FFN>>>(d_xt, d_w1t, b1);
    ffn_mma<2><<<dim3(Dq/128, 3, Eq*Bq), 256, SMEM_FFN>>>(d_h,  d_w2t, b2);

    combine_kernel<<<NTOK, 256>>>(out);
}

// round 9
// speedup vs baseline: 2.2472x; 2.2472x over previous
#include <cuda_runtime.h>
#include <math.h>
#include <cstdint>

#define Bq   8
#define Nq   2048
#define Dq   1024
#define Eq   8
#define Hq   4096
#define CAP  320
#define NTOK (Bq*Nq)
#define OUT_MAIN ((size_t)NTOK*Dq)

__device__ int   d_meta[NTOK];
__device__ float d_g1[NTOK];
__device__ float d_g2[NTOK];
__device__ int   d_a1[NTOK];
__device__ int   d_a2[NTOK];
__device__ float d_proxy[Bq*Eq];
__device__ int   d_slotTok[Eq*Bq*CAP];
__device__ float d_h  [(size_t)Eq*Bq*CAP*Hq];   // tf32-valued post-GELU hidden
__device__ float d_eo [(size_t)Eq*Bq*CAP*Dq];
__device__ float d_xt [(size_t)NTOK*Dq];        // tf32-rounded x
__device__ float d_w1t[(size_t)Eq*Dq*Hq];       // [e][n][k] tf32
__device__ float d_w2t[(size_t)Eq*Hq*Dq];       // [e][n][k] tf32
__device__ float d_zero[4352];                  // static zero-init (>= max Kdim)

// ---------------- helpers ----------------
__device__ __forceinline__ uint32_t smem_u32(const void* p) {
    uint32_t a;
    asm("{ .reg .u64 t; cvta.to.shared.u64 t, %1; cvt.u32.u64 %0, t; }" : "=r"(a) : "l"(p));
    return a;
}
__device__ __forceinline__ uint32_t f2tf32(float x) {
    uint32_t r;
    asm("cvt.rna.tf32.f32 %0, %1;" : "=r"(r) : "f"(x));
    return r;
}
__device__ __forceinline__ void mma_tf32(float* d, const uint32_t* a, const uint32_t* b) {
    asm volatile(
        "mma.sync.aligned.m16n8k8.row.col.f32.tf32.tf32.f32 "
        "{%0,%1,%2,%3}, {%4,%5,%6,%7}, {%8,%9}, {%0,%1,%2,%3};\n"
        : "+f"(d[0]), "+f"(d[1]), "+f"(d[2]), "+f"(d[3])
        : "r"(a[0]), "r"(a[1]), "r"(a[2]), "r"(a[3]), "r"(b[0]), "r"(b[1]));
}
__device__ __forceinline__ void ldsm4(uint32_t* r, uint32_t addr) {
    asm volatile("ldmatrix.sync.aligned.m8n8.x4.shared.b16 {%0,%1,%2,%3}, [%4];"
        : "=r"(r[0]), "=r"(r[1]), "=r"(r[2]), "=r"(r[3]) : "r"(addr));
}

// ---------------- init ----------------
__global__ void init_kernel() {
    int t = threadIdx.x;
    if (t < Bq*Eq) d_proxy[t] = 0.f;
}

// ---------------- pre-convert x -> tf32 ----------------
__global__ __launch_bounds__(256) void conv_x(const float* __restrict__ x) {
    size_t i = ((size_t)blockIdx.x * 256 + threadIdx.x) * 4;
    float4 v = *(const float4*)(x + i);
    v.x = __uint_as_float(f2tf32(v.x));
    v.y = __uint_as_float(f2tf32(v.y));
    v.z = __uint_as_float(f2tf32(v.z));
    v.w = __uint_as_float(f2tf32(v.w));
    *(float4*)(d_xt + i) = v;
}

// ---------------- pre-convert + transpose weights: Wt[e][n][k] = rna(W[e][k][n]) ----------------
template<int Kd, int Nc>
__global__ __launch_bounds__(256) void conv_w(const float* __restrict__ W, float* __restrict__ Wt) {
    __shared__ float t[32][33];
    const int e  = blockIdx.z;
    const int k0 = blockIdx.y * 32, n0 = blockIdx.x * 32;
    const float* src = W  + (size_t)e * Kd * Nc;
    float*       dst = Wt + (size_t)e * Kd * Nc;
    const int lx = threadIdx.x & 31, ly = threadIdx.x >> 5;
    #pragma unroll
    for (int yy = ly; yy < 32; yy += 8)
        t[yy][lx] = src[(size_t)(k0 + yy) * Nc + n0 + lx];
    __syncthreads();
    #pragma unroll
    for (int yy = ly; yy < 32; yy += 8)
        dst[(size_t)(n0 + yy) * Kd + k0 + lx] = __uint_as_float(f2tf32(t[lx][yy]));
}

// ---------------- gating ----------------
__global__ __launch_bounds__(256) void gating_kernel(
    const float* __restrict__ x, const float* __restrict__ wg,
    const float* __restrict__ rnd)
{
    __shared__ float s_wg[Eq][Dq];
    __shared__ float s_proxy[Eq];
    int tid = threadIdx.x;
    for (int f = tid; f < Dq*Eq; f += 256) {
        int d = f >> 3, e = f & 7;
        s_wg[e][d] = wg[f];
    }
    if (tid < Eq) s_proxy[tid] = 0.f;
    __syncthreads();

    int warp = tid >> 5, lane = tid & 31;
    int tok  = blockIdx.x * 8 + warp;
    const float* xp = x + (size_t)tok * Dq;

    float acc[Eq];
    #pragma unroll
    for (int e = 0; e < Eq; ++e) acc[e] = 0.f;
    #pragma unroll 4
    for (int i = 0; i < Dq/32; ++i) {
        float xv = xp[i*32 + lane];
        #pragma unroll
        for (int e = 0; e < Eq; ++e) acc[e] += xv * s_wg[e][i*32 + lane];
    }
    #pragma unroll
    for (int off = 16; off; off >>= 1)
        #pragma unroll
        for (int e = 0; e < Eq; ++e)
            acc[e] += __shfl_down_sync(0xffffffffu, acc[e], off);

    if (lane == 0) {
        float mx = acc[0];
        #pragma unroll
        for (int e = 1; e < Eq; ++e) mx = fmaxf(mx, acc[e]);
        float raw[Eq]; float s = 0.f;
        #pragma unroll
        for (int e = 0; e < Eq; ++e) { raw[e] = expf(acc[e] - mx); s += raw[e]; }
        float inv = 1.f / s;
        #pragma unroll
        for (int e = 0; e < Eq; ++e) raw[e] *= inv;
        int i1 = 0; float g1 = raw[0];
        #pragma unroll
        for (int e = 1; e < Eq; ++e) if (raw[e] > g1) { g1 = raw[e]; i1 = e; }
        int i2 = -1; float g2 = -1.f;
        #pragma unroll
        for (int e = 0; e < Eq; ++e) if (e != i1 && raw[e] > g2) { g2 = raw[e]; i2 = e; }
        float denom = g1 + g2 + 1e-9f;
        float g1n = g1 / denom, g2n = g2 / denom;
        int keep2 = (rnd[tok] < (g2n / 0.2f)) ? 1 : 0;
        d_meta[tok] = i1 | (i2 << 4) | (keep2 << 8);
        d_g1[tok] = g1n;
        d_g2[tok] = g2n;
        #pragma unroll
        for (int e = 0; e < Eq; ++e) atomicAdd(&s_proxy[e], raw[e]);
    }
    __syncthreads();
    if (tid < Eq) {
        int b = (blockIdx.x * 8) >> 11;
        atomicAdd(&d_proxy[b*Eq + tid], s_proxy[tid]);
    }
}

// ---------------- scan ----------------
__global__ void scan_kernel(float* __restrict__ dout, int out_size)
{
    __shared__ int   s_meta[2048];
    __shared__ float s_red[64];
    int t = threadIdx.x;
    int b = t >> 3, e = t & 7;
    int g = e * Bq + b;
    for (int j = 0; j < CAP; ++j) d_slotTok[g*CAP + j] = -1;
    int c1 = 0;
    for (int ch = 0; ch < 8; ++ch) {
        __syncthreads();
        for (int i = t; i < 2048; i += 64) {
            int bb = i >> 8, ii = i & 255;
            s_meta[i] = d_meta[bb*Nq + ch*256 + ii];
        }
        __syncthreads();
        for (int ii = 0; ii < 256; ++ii) {
            int meta = s_meta[b*256 + ii];
            if ((meta & 15) == e) {
                int n = ch*256 + ii;
                if (c1 < CAP) {
                    d_slotTok[g*CAP + c1] = n;
                    d_a1[b*Nq + n] = (e << 10) | c1;
                } else d_a1[b*Nq + n] = -1;
                c1++;
            }
        }
    }
    int c1raw = c1;
    int pos = (c1 < CAP) ? c1 : CAP;
    for (int ch = 0; ch < 8; ++ch) {
        __syncthreads();
        for (int i = t; i < 2048; i += 64) {
            int bb = i >> 8, ii = i & 255;
            s_meta[i] = d_meta[bb*Nq + ch*256 + ii];
        }
        __syncthreads();
        for (int ii = 0; ii < 256; ++ii) {
            int meta = s_meta[b*256 + ii];
            if (((meta >> 4) & 15) == e) {
                int n = ch*256 + ii;
                if ((meta >> 8) & 1) {
                    if (pos < CAP) {
                        d_slotTok[g*CAP + pos] = n;
                        d_a2[b*Nq + n] = (e << 10) | pos;
                    } else d_a2[b*Nq + n] = -1;
                    pos++;
                } else d_a2[b*Nq + n] = -1;
            }
        }
    }
    s_red[t] = (d_proxy[b*Eq + e] / (float)Nq) * ((float)c1raw / (float)Nq);
    __syncthreads();
    if (t == 0) {
        float s = 0.f;
        for (int i = 0; i < 64; ++i) s += s_red[i];
        if ((size_t)out_size > OUT_MAIN) dout[OUT_MAIN] = s * 0.01f;
    }
}

// ---------------- tf32 mma.sync grouped GEMM (round-5 verified mainloop) ----------------
// CTA 128x128, K in 32-chunks, 2-stage double buffer w/ register prefetch.
// 8 warps (2m x 4n), warp 64x32, mma m16n8k8, ldmatrix fragments.
// SMEM bytes: sA[2][16384] @0      (A[row][k] 128x32 tf32, off=row*128+16*(slot^(row&7)))
//             sB[2][16384] @32768  (B[n][k]  128x32 tf32, same swizzle)
//             sPtr @65536 (1KB), sBias @66560 (512B)
// Operands pre-converted to tf32 (no cvt in loop); B pre-transposed -> LDG.128;
// STS are 16B vector stores (conflict-free per phase: slot^(row&7) injective).
#define SMEM_FFN 67072

template<int PHASE>
__global__ __launch_bounds__(256, 1) void ffn_mma(const float* __restrict__ A_src,
                                                  const float* __restrict__ Wt,
                                                  const float* __restrict__ Bias)
{
    constexpr int Kdim  = (PHASE == 1) ? Dq : Hq;
    constexpr int Ncols = (PHASE == 1) ? Hq : Dq;
    constexpr int NCH   = Kdim / 32;

    extern __shared__ char smem[];
    const float** sPtr  = (const float**)(smem + 65536);
    float*        sBias = (float*)(smem + 66560);

    const int tid  = threadIdx.x;
    const int wid  = tid >> 5, lane = tid & 31;
    const int g8   = lane >> 2, tg = lane & 3;
    const int n0   = blockIdx.x * 128;
    const int m0   = blockIdx.y * 128;
    const int grp  = blockIdx.z;
    const int e    = grp >> 3, b = grp & 7;
    const int wm   = wid & 1, wn = wid >> 1;
    const bool active = (m0 + wm*64) < CAP;

    if (tid < 128) {
        int c = m0 + tid;
        const float* p = d_zero;
        if (c < CAP) {
            if (PHASE == 1) {
                int tok = d_slotTok[grp*CAP + c];
                if (tok >= 0) p = d_xt + ((size_t)(b*Nq) + tok) * Dq;
            } else {
                p = d_h + ((size_t)grp*CAP + c) * Hq;
            }
        }
        sPtr[tid]  = p;
        sBias[tid] = Bias[(size_t)e * Ncols + n0 + tid];
    }
    __syncthreads();

    const uint32_t sb = smem_u32(smem);

    // global-load / SMEM-store geometry: A and B symmetric (128 rows x 32 k)
    const int row = tid >> 1, fb = (tid & 1) * 4;   // row 0..127, 16B-slot base 0/4
    const float* aRow = sPtr[row];
    const float* bRow = Wt + (size_t)e * Kdim * Ncols + (size_t)(n0 + row) * Kdim;
    uint32_t stRel[4];
    #pragma unroll
    for (int i = 0; i < 4; ++i)
        stRel[i] = (uint32_t)(row*128 + 16*((fb + i) ^ (row & 7)));

    float4 rA[4], rB[4];

    #define LDA(ch) do { \
        _Pragma("unroll") \
        for (int i = 0; i < 4; ++i) \
            rA[i] = *(const float4*)(aRow + (ch)*32 + (fb + i)*4); \
        } while (0)
    #define LDB(ch) do { \
        _Pragma("unroll") \
        for (int i = 0; i < 4; ++i) \
            rB[i] = *(const float4*)(bRow + (ch)*32 + (fb + i)*4); \
        } while (0)
    #define STA(buf) do { \
        _Pragma("unroll") \
        for (int i = 0; i < 4; ++i) \
            *(float4*)(smem + (buf)*16384 + stRel[i]) = rA[i]; \
        } while (0)
    #define STB(buf) do { \
        _Pragma("unroll") \
        for (int i = 0; i < 4; ++i) \
            *(float4*)(smem + 32768 + (buf)*16384 + stRel[i]) = rB[i]; \
        } while (0)

    // ldmatrix geometry (identical to round 5)
    const int hiA = lane >> 4;
    const uint32_t aBase = sb + (uint32_t)(wm*64 + ((lane>>3)&1)*8 + (lane&7)) * 128u;
    const uint32_t bBase = sb + 32768u + (uint32_t)(wn*32 + (lane>>4)*8 + (lane&7)) * 128u;
    uint32_t aSw[4], bSw[4];
    #pragma unroll
    for (int ks = 0; ks < 4; ++ks) {
        aSw[ks] = 16u * (uint32_t)((2*ks + hiA) ^ (lane & 7));
        bSw[ks] = 16u * (uint32_t)((2*ks + ((lane>>3)&1)) ^ (lane & 7));
    }

    float acc[4][4][4];
    #pragma unroll
    for (int mi = 0; mi < 4; ++mi)
        #pragma unroll
        for (int ni = 0; ni < 4; ++ni)
            #pragma unroll
            for (int q = 0; q < 4; ++q) acc[mi][ni][q] = 0.f;

    LDA(0); LDB(0);
    STA(0); STB(0);
    __syncthreads();

    for (int ch = 0; ch < NCH; ++ch) {
        const uint32_t bufOff = (ch & 1) ? 16384u : 0u;
        if (ch + 1 < NCH) { LDA(ch + 1); LDB(ch + 1); }

        if (active) {
            #pragma unroll
            for (int ks = 0; ks < 4; ++ks) {
                uint32_t af[4][4], bf[2][4];
                const uint32_t ao = bufOff + aSw[ks];
                const uint32_t bo = bufOff + bSw[ks];
                #pragma unroll
                for (int mi = 0; mi < 4; ++mi)
                    ldsm4(af[mi], aBase + (uint32_t)(mi*2048) + ao);
                ldsm4(bf[0], bBase + bo);
                ldsm4(bf[1], bBase + 2048u + bo);
                #pragma unroll
                for (int mi = 0; mi < 4; ++mi) {
                    mma_tf32(acc[mi][0], af[mi], &bf[0][0]);
                    mma_tf32(acc[mi][1], af[mi], &bf[0][2]);
                    mma_tf32(acc[mi][2], af[mi], &bf[1][0]);
                    mma_tf32(acc[mi][3], af[mi], &bf[1][2]);
                }
            }
        }

        if (ch + 1 < NCH) { STA((ch + 1) & 1); STB((ch + 1) & 1); }
        __syncthreads();
    }
    #undef LDA
    #undef LDB
    #undef STA
    #undef STB

    // epilogue: bias (+GELU phase1), direct float2 stores
    float* Outp = (PHASE == 1) ? d_h : d_eo;
    #pragma unroll
    for (int mi = 0; mi < 4; ++mi) {
        #pragma unroll
        for (int h = 0; h < 2; ++h) {
            int c = m0 + wm*64 + mi*16 + g8 + h*8;
            if (c < CAP) {
                float* orow = Outp + ((size_t)grp*CAP + c) * Ncols + n0;
                #pragma unroll
                for (int ni = 0; ni < 4; ++ni) {
                    int col = wn*32 + ni*8 + 2*tg;
                    float v0 = acc[mi][ni][2*h]     + sBias[col];
                    float v1 = acc[mi][ni][2*h + 1] + sBias[col + 1];
                    if (PHASE == 1) {
                        v0 = 0.5f * v0 * (1.0f + erff(v0 * 0.70710678118654752f));
                        v1 = 0.5f * v1 * (1.0f + erff(v1 * 0.70710678118654752f));
                        v0 = __uint_as_float(f2tf32(v0));   // d_h feeds GEMM2 as tf32
                        v1 = __uint_as_float(f2tf32(v1));
                    }
                    float2 v = make_float2(v0, v1);
                    *(float2*)(orow + col) = v;
                }
            }
        }
    }
}

// ---------------- combine ----------------
__global__ __launch_bounds__(256) void combine_kernel(float* __restrict__ out)
{
    int tok = blockIdx.x;
    int b   = tok >> 11;
    int a1  = d_a1[tok], a2 = d_a2[tok];
    float g1 = d_g1[tok], g2 = d_g2[tok];
    int off = threadIdx.x * 4;

    float4 v = make_float4(0.f, 0.f, 0.f, 0.f);
    if (a1 >= 0) {
        size_t row = ((size_t)((a1 >> 10) * Bq + b)) * CAP + (a1 & 1023);
        const float4 s = *(const float4*)(d_eo + row * Dq + off);
        v.x = g1 * s.x; v.y = g1 * s.y; v.z = g1 * s.z; v.w = g1 * s.w;
    }
    if (a2 >= 0) {
        size_t row = ((size_t)((a2 >> 10) * Bq + b)) * CAP + (a2 & 1023);
        const float4 s = *(const float4*)(d_eo + row * Dq + off);
        v.x += g2 * s.x; v.y += g2 * s.y; v.z += g2 * s.z; v.w += g2 * s.w;
    }
    *(float4*)(out + (size_t)tok * Dq + off) = v;
}

// ---------------- launch ----------------
extern "C" void kernel_launch(void* const* d_in, const int* in_sizes, int n_in,
                              void* d_out, int out_size)
{
    const float* x  = (const float*)d_in[0];
    const float* wg = (const float*)d_in[1];
    const float* w1 = (const float*)d_in[2];
    const float* b1 = (const float*)d_in[3];
    const float* w2 = (const float*)d_in[4];
    const float* b2 = (const float*)d_in[5];
    const float* rp = (const float*)d_in[6];
    float* out = (float*)d_out;

    cudaFuncSetAttribute(ffn_mma<1>, cudaFuncAttributeMaxDynamicSharedMemorySize, SMEM_FFN);
    cudaFuncSetAttribute(ffn_mma<2>, cudaFuncAttributeMaxDynamicSharedMemorySize, SMEM_FFN);

    init_kernel<<<1, 64>>>();
    conv_x<<<NTOK*Dq/1024, 256>>>(x);
    conv_w<Dq, Hq><<<dim3(Hq/32, Dq/32, Eq), 256>>>(w1, d_w1t);
    conv_w<Hq, Dq><<<dim3(Dq/32, Hq/32, Eq), 256>>>(w2, d_w2t);
    gating_kernel<<<NTOK/8, 256>>>(x, wg, rp);
    scan_kernel<<<1, 64>>>(out, out_size);

    ffn_mma<1><<<dim3(Hq/128, 3, Eq*Bq), 256, SMEM_FFN>>>(d_xt, d_w1t, b1);
    ffn_mma<2><<<dim3(Dq/128, 3, Eq*Bq), 256, SMEM_FFN>>>(d_h,  d_w2t, b2);

    combine_kernel<<<NTOK, 256>>>(out);
}

// round 10
// speedup vs baseline: 26.0640x; 11.5982x over previous
#include <cuda_runtime.h>
#include <math.h>
#include <cstdint>

#define Bq   8
#define Nq   2048
#define Dq   1024
#define Eq   8
#define Hq   4096
#define CAP  320
#define NTOK (Bq*Nq)
#define OUT_MAIN ((size_t)NTOK*Dq)

// ---- scratch: EXACTLY the round-5 set (no extra giant globals) ----
__device__ int   d_meta[NTOK];
__device__ float d_g1[NTOK];
__device__ float d_g2[NTOK];
__device__ int   d_a1[NTOK];
__device__ int   d_a2[NTOK];
__device__ float d_proxy[Bq*Eq];
__device__ int   d_slotTok[Eq*Bq*CAP];
__device__ float d_h [(size_t)Eq*Bq*CAP*Hq];   // tf32-valued post-GELU hidden
__device__ float d_eo[(size_t)Eq*Bq*CAP*Dq];

// ---------------- helpers ----------------
__device__ __forceinline__ uint32_t smem_u32(const void* p) {
    uint32_t a;
    asm("{ .reg .u64 t; cvta.to.shared.u64 t, %1; cvt.u32.u64 %0, t; }" : "=r"(a) : "l"(p));
    return a;
}
__device__ __forceinline__ uint32_t f2tf32(float x) {
    uint32_t r;
    asm("cvt.rna.tf32.f32 %0, %1;" : "=r"(r) : "f"(x));
    return r;
}
__device__ __forceinline__ float tf32v(float x) {
    return __uint_as_float(f2tf32(x));
}
__device__ __forceinline__ void mma_tf32(float* d, const uint32_t* a, const uint32_t* b) {
    asm volatile(
        "mma.sync.aligned.m16n8k8.row.col.f32.tf32.tf32.f32 "
        "{%0,%1,%2,%3}, {%4,%5,%6,%7}, {%8,%9}, {%0,%1,%2,%3};\n"
        : "+f"(d[0]), "+f"(d[1]), "+f"(d[2]), "+f"(d[3])
        : "r"(a[0]), "r"(a[1]), "r"(a[2]), "r"(a[3]), "r"(b[0]), "r"(b[1]));
}
__device__ __forceinline__ void ldsm4(uint32_t* r, uint32_t addr) {
    asm volatile("ldmatrix.sync.aligned.m8n8.x4.shared.b16 {%0,%1,%2,%3}, [%4];"
        : "=r"(r[0]), "=r"(r[1]), "=r"(r[2]), "=r"(r[3]) : "r"(addr));
}

// ---------------- init ----------------
__global__ void init_kernel() {
    int t = threadIdx.x;
    if (t < Bq*Eq) d_proxy[t] = 0.f;
}

// ---------------- gating ----------------
__global__ __launch_bounds__(256) void gating_kernel(
    const float* __restrict__ x, const float* __restrict__ wg,
    const float* __restrict__ rnd)
{
    __shared__ float s_wg[Eq][Dq];
    __shared__ float s_proxy[Eq];
    int tid = threadIdx.x;
    for (int f = tid; f < Dq*Eq; f += 256) {
        int d = f >> 3, e = f & 7;
        s_wg[e][d] = wg[f];
    }
    if (tid < Eq) s_proxy[tid] = 0.f;
    __syncthreads();

    int warp = tid >> 5, lane = tid & 31;
    int tok  = blockIdx.x * 8 + warp;
    const float* xp = x + (size_t)tok * Dq;

    float acc[Eq];
    #pragma unroll
    for (int e = 0; e < Eq; ++e) acc[e] = 0.f;
    #pragma unroll 4
    for (int i = 0; i < Dq/32; ++i) {
        float xv = xp[i*32 + lane];
        #pragma unroll
        for (int e = 0; e < Eq; ++e) acc[e] += xv * s_wg[e][i*32 + lane];
    }
    #pragma unroll
    for (int off = 16; off; off >>= 1)
        #pragma unroll
        for (int e = 0; e < Eq; ++e)
            acc[e] += __shfl_down_sync(0xffffffffu, acc[e], off);

    if (lane == 0) {
        float mx = acc[0];
        #pragma unroll
        for (int e = 1; e < Eq; ++e) mx = fmaxf(mx, acc[e]);
        float raw[Eq]; float s = 0.f;
        #pragma unroll
        for (int e = 0; e < Eq; ++e) { raw[e] = expf(acc[e] - mx); s += raw[e]; }
        float inv = 1.f / s;
        #pragma unroll
        for (int e = 0; e < Eq; ++e) raw[e] *= inv;
        int i1 = 0; float g1 = raw[0];
        #pragma unroll
        for (int e = 1; e < Eq; ++e) if (raw[e] > g1) { g1 = raw[e]; i1 = e; }
        int i2 = -1; float g2 = -1.f;
        #pragma unroll
        for (int e = 0; e < Eq; ++e) if (e != i1 && raw[e] > g2) { g2 = raw[e]; i2 = e; }
        float denom = g1 + g2 + 1e-9f;
        float g1n = g1 / denom, g2n = g2 / denom;
        int keep2 = (rnd[tok] < (g2n / 0.2f)) ? 1 : 0;
        d_meta[tok] = i1 | (i2 << 4) | (keep2 << 8);
        d_g1[tok] = g1n;
        d_g2[tok] = g2n;
        #pragma unroll
        for (int e = 0; e < Eq; ++e) atomicAdd(&s_proxy[e], raw[e]);
    }
    __syncthreads();
    if (tid < Eq) {
        int b = (blockIdx.x * 8) >> 11;
        atomicAdd(&d_proxy[b*Eq + tid], s_proxy[tid]);
    }
}

// ---------------- scan ----------------
__global__ void scan_kernel(float* __restrict__ dout, int out_size)
{
    __shared__ int   s_meta[2048];
    __shared__ float s_red[64];
    int t = threadIdx.x;
    int b = t >> 3, e = t & 7;
    int g = e * Bq + b;
    for (int j = 0; j < CAP; ++j) d_slotTok[g*CAP + j] = -1;
    int c1 = 0;
    for (int ch = 0; ch < 8; ++ch) {
        __syncthreads();
        for (int i = t; i < 2048; i += 64) {
            int bb = i >> 8, ii = i & 255;
            s_meta[i] = d_meta[bb*Nq + ch*256 + ii];
        }
        __syncthreads();
        for (int ii = 0; ii < 256; ++ii) {
            int meta = s_meta[b*256 + ii];
            if ((meta & 15) == e) {
                int n = ch*256 + ii;
                if (c1 < CAP) {
                    d_slotTok[g*CAP + c1] = n;
                    d_a1[b*Nq + n] = (e << 10) | c1;
                } else d_a1[b*Nq + n] = -1;
                c1++;
            }
        }
    }
    int c1raw = c1;
    int pos = (c1 < CAP) ? c1 : CAP;
    for (int ch = 0; ch < 8; ++ch) {
        __syncthreads();
        for (int i = t; i < 2048; i += 64) {
            int bb = i >> 8, ii = i & 255;
            s_meta[i] = d_meta[bb*Nq + ch*256 + ii];
        }
        __syncthreads();
        for (int ii = 0; ii < 256; ++ii) {
            int meta = s_meta[b*256 + ii];
            if (((meta >> 4) & 15) == e) {
                int n = ch*256 + ii;
                if ((meta >> 8) & 1) {
                    if (pos < CAP) {
                        d_slotTok[g*CAP + pos] = n;
                        d_a2[b*Nq + n] = (e << 10) | pos;
                    } else d_a2[b*Nq + n] = -1;
                    pos++;
                } else d_a2[b*Nq + n] = -1;
            }
        }
    }
    s_red[t] = (d_proxy[b*Eq + e] / (float)Nq) * ((float)c1raw / (float)Nq);
    __syncthreads();
    if (t == 0) {
        float s = 0.f;
        for (int i = 0; i < 64; ++i) s += s_red[i];
        if ((size_t)out_size > OUT_MAIN) dout[OUT_MAIN] = s * 0.01f;
    }
}

// ---------------- tf32 mma.sync grouped GEMM (round-5 structure, vector STS) ----------------
// CTA 128x128, K in 32-chunks, 2-stage double buffer, 8 warps (2m x 4n), warp 64x32.
// SMEM: sA[2][16384] @0 (A[row][k], off=row*128+16*(slot^(row&7)), slot=k/4)
//       sB[2][16384] @32768 (B[n][k], same swizzle)
//       sPtr @65536 (1KB), sBias @66560 (512B)
// A: LDG.128 from X (phase1, gathered, raw fp32 -> cvt) or d_h (phase2, tf32-valued, no cvt).
// B: 4 coalesced scalar LDG (k-strided at fixed n) -> cvt -> ONE STS.128.
#define SMEM_FFN 67072

template<int PHASE>
__global__ __launch_bounds__(256, 1) void ffn_mma(const float* __restrict__ X,
                                                  const float* __restrict__ W,
                                                  const float* __restrict__ Bias)
{
    constexpr int Kdim  = (PHASE == 1) ? Dq : Hq;
    constexpr int Ncols = (PHASE == 1) ? Hq : Dq;
    constexpr int NCH   = Kdim / 32;

    extern __shared__ char smem[];
    const float** sPtr  = (const float**)(smem + 65536);
    float*        sBias = (float*)(smem + 66560);

    const int tid  = threadIdx.x;
    const int wid  = tid >> 5, lane = tid & 31;
    const int g8   = lane >> 2, tg = lane & 3;
    const int n0   = blockIdx.x * 128;
    const int m0   = blockIdx.y * 128;
    const int grp  = blockIdx.z;
    const int e    = grp >> 3, b = grp & 7;
    const int wm   = wid & 1, wn = wid >> 1;
    const bool active = (m0 + wm*64) < CAP;

    if (tid < 128) {
        int c = m0 + tid;
        const float* p = nullptr;
        if (c < CAP) {
            if (PHASE == 1) {
                int tok = d_slotTok[grp*CAP + c];
                if (tok >= 0) p = X + ((size_t)(b*Nq) + tok) * Dq;
            } else {
                p = d_h + ((size_t)grp*CAP + c) * Hq;
            }
        }
        sPtr[tid]  = p;
        sBias[tid] = Bias[(size_t)e * Ncols + n0 + tid];
    }
    __syncthreads();

    const uint32_t sb = smem_u32(smem);

    // A fill geometry: row = tid>>1 (0..127), slot base fb = 0/4
    const int row = tid >> 1, fb = (tid & 1) * 4;
    const float* aRow = sPtr[row];
    uint32_t stRel[4];
    #pragma unroll
    for (int i = 0; i < 4; ++i)
        stRel[i] = (uint32_t)(row*128 + 16*((fb + i) ^ (row & 7)));

    // B fill geometry: n = tid&127, kq slots {bkq, 2+bkq, 4+bkq, 6+bkq}
    const int bn  = tid & 127;
    const int bkq = tid >> 7;
    const float* Wg = W + (size_t)e * Kdim * Ncols + n0;
    uint32_t bRel[4];
    #pragma unroll
    for (int i = 0; i < 4; ++i)
        bRel[i] = (uint32_t)(bn*128 + 16*(((i*2 + bkq)) ^ (bn & 7)));

    float4 rA[4], rB[4];

    #define LDA(ch) do { \
        _Pragma("unroll") \
        for (int i = 0; i < 4; ++i) { \
            if (aRow) rA[i] = *(const float4*)(aRow + (ch)*32 + (fb + i)*4); \
            else      rA[i] = make_float4(0.f, 0.f, 0.f, 0.f); \
        } } while (0)
    #define LDB(ch) do { \
        _Pragma("unroll") \
        for (int i = 0; i < 4; ++i) { \
            const float* wp = Wg + (size_t)((ch)*32 + (i*2 + bkq)*4) * Ncols + bn; \
            rB[i].x = wp[0]; \
            rB[i].y = wp[Ncols]; \
            rB[i].z = wp[(size_t)2*Ncols]; \
            rB[i].w = wp[(size_t)3*Ncols]; \
        } } while (0)
    #define STA(buf) do { \
        _Pragma("unroll") \
        for (int i = 0; i < 4; ++i) { \
            float4 v = rA[i]; \
            if (PHASE == 1) { \
                v.x = tf32v(v.x); v.y = tf32v(v.y); \
                v.z = tf32v(v.z); v.w = tf32v(v.w); \
            } \
            *(float4*)(smem + (buf)*16384 + stRel[i]) = v; \
        } } while (0)
    #define STB(buf) do { \
        _Pragma("unroll") \
        for (int i = 0; i < 4; ++i) { \
            float4 v; \
            v.x = tf32v(rB[i].x); v.y = tf32v(rB[i].y); \
            v.z = tf32v(rB[i].z); v.w = tf32v(rB[i].w); \
            *(float4*)(smem + 32768 + (buf)*16384 + bRel[i]) = v; \
        } } while (0)

    // ldmatrix geometry (validated in rounds 5/9)
    const int hiA = lane >> 4;
    const uint32_t aBase = sb + (uint32_t)(wm*64 + ((lane>>3)&1)*8 + (lane&7)) * 128u;
    const uint32_t bBase = sb + 32768u + (uint32_t)(wn*32 + (lane>>4)*8 + (lane&7)) * 128u;
    uint32_t aSw[4], bSw[4];
    #pragma unroll
    for (int ks = 0; ks < 4; ++ks) {
        aSw[ks] = 16u * (uint32_t)((2*ks + hiA) ^ (lane & 7));
        bSw[ks] = 16u * (uint32_t)((2*ks + ((lane>>3)&1)) ^ (lane & 7));
    }

    float acc[4][4][4];
    #pragma unroll
    for (int mi = 0; mi < 4; ++mi)
        #pragma unroll
        for (int ni = 0; ni < 4; ++ni)
            #pragma unroll
            for (int q = 0; q < 4; ++q) acc[mi][ni][q] = 0.f;

    LDA(0); LDB(0);
    STA(0); STB(0);
    __syncthreads();

    for (int ch = 0; ch < NCH; ++ch) {
        const uint32_t bufOff = (ch & 1) ? 16384u : 0u;
        if (ch + 1 < NCH) { LDA(ch + 1); LDB(ch + 1); }

        if (active) {
            #pragma unroll
            for (int ks = 0; ks < 4; ++ks) {
                uint32_t af[4][4], bf[2][4];
                const uint32_t ao = bufOff + aSw[ks];
                const uint32_t bo = bufOff + bSw[ks];
                #pragma unroll
                for (int mi = 0; mi < 4; ++mi)
                    ldsm4(af[mi], aBase + (uint32_t)(mi*2048) + ao);
                ldsm4(bf[0], bBase + bo);
                ldsm4(bf[1], bBase + 2048u + bo);
                #pragma unroll
                for (int mi = 0; mi < 4; ++mi) {
                    mma_tf32(acc[mi][0], af[mi], &bf[0][0]);
                    mma_tf32(acc[mi][1], af[mi], &bf[0][2]);
                    mma_tf32(acc[mi][2], af[mi], &bf[1][0]);
                    mma_tf32(acc[mi][3], af[mi], &bf[1][2]);
                }
            }
        }

        if (ch + 1 < NCH) { STA((ch + 1) & 1); STB((ch + 1) & 1); }
        __syncthreads();
    }
    #undef LDA
    #undef LDB
    #undef STA
    #undef STB

    // epilogue: bias (+GELU phase1, tf32-round d_h so phase2 skips A-side cvt)
    float* Outp = (PHASE == 1) ? d_h : d_eo;
    #pragma unroll
    for (int mi = 0; mi < 4; ++mi) {
        #pragma unroll
        for (int h = 0; h < 2; ++h) {
            int c = m0 + wm*64 + mi*16 + g8 + h*8;
            if (c < CAP) {
                float* orow = Outp + ((size_t)grp*CAP + c) * Ncols + n0;
                #pragma unroll
                for (int ni = 0; ni < 4; ++ni) {
                    int col = wn*32 + ni*8 + 2*tg;
                    float v0 = acc[mi][ni][2*h]     + sBias[col];
                    float v1 = acc[mi][ni][2*h + 1] + sBias[col + 1];
                    if (PHASE == 1) {
                        v0 = 0.5f * v0 * (1.0f + erff(v0 * 0.70710678118654752f));
                        v1 = 0.5f * v1 * (1.0f + erff(v1 * 0.70710678118654752f));
                        v0 = tf32v(v0);
                        v1 = tf32v(v1);
                    }
                    float2 v = make_float2(v0, v1);
                    *(float2*)(orow + col) = v;
                }
            }
        }
    }
}

// ---------------- combine ----------------
__global__ __launch_bounds__(256) void combine_kernel(float* __restrict__ out)
{
    int tok = blockIdx.x;
    int b   = tok >> 11;
    int a1  = d_a1[tok], a2 = d_a2[tok];
    float g1 = d_g1[tok], g2 = d_g2[tok];
    int off = threadIdx.x * 4;

    float4 v = make_float4(0.f, 0.f, 0.f, 0.f);
    if (a1 >= 0) {
        size_t row = ((size_t)((a1 >> 10) * Bq + b)) * CAP + (a1 & 1023);
        const float4 s = *(const float4*)(d_eo + row * Dq + off);
        v.x = g1 * s.x; v.y = g1 * s.y; v.z = g1 * s.z; v.w = g1 * s.w;
    }
    if (a2 >= 0) {
        size_t row = ((size_t)((a2 >> 10) * Bq + b)) * CAP + (a2 & 1023);
        const float4 s = *(const float4*)(d_eo + row * Dq + off);
        v.x += g2 * s.x; v.y += g2 * s.y; v.z += g2 * s.z; v.w += g2 * s.w;
    }
    *(float4*)(out + (size_t)tok * Dq + off) = v;
}

// ---------------- launch (round-5 sequence: no pre-convert kernels) ----------------
extern "C" void kernel_launch(void* const* d_in, const int* in_sizes, int n_in,
                              void* d_out, int out_size)
{
    const float* x  = (const float*)d_in[0];
    const float* wg = (const float*)d_in[1];
    const float* w1 = (const float*)d_in[2];
    const float* b1 = (const float*)d_in[3];
    const float* w2 = (const float*)d_in[4];
    const float* b2 = (const float*)d_in[5];
    const float* rp = (const float*)d_in[6];
    float* out = (float*)d_out;

    cudaFuncSetAttribute(ffn_mma<1>, cudaFuncAttributeMaxDynamicSharedMemorySize, SMEM_FFN);
    cudaFuncSetAttribute(ffn_mma<2>, cudaFuncAttributeMaxDynamicSharedMemorySize, SMEM_FFN);

    init_kernel<<<1, 64>>>();
    gating_kernel<<<NTOK/8, 256>>>(x, wg, rp);
    scan_kernel<<<1, 64>>>(out, out_size);

    ffn_mma<1><<<dim3(Hq/128, 3, Eq*Bq), 256, SMEM_FFN>>>(x, w1, b1);
    ffn_mma<2><<<dim3(Dq/128, 3, Eq*Bq), 256, SMEM_FFN>>>(d_h, w2, b2);

    combine_kernel<<<NTOK, 256>>>(out);
}